// round 8
// baseline (speedup 1.0000x reference)
#include <cuda_runtime.h>
#include <cuda_bf16.h>
#include <math.h>

// ----------------------------------------------------------------------------
// AdaptiveFeaturePropagation  (f32x2, 8oc x 8px register blocking)
// ----------------------------------------------------------------------------

#define Hc 129
#define Wc 129
#define HWc (129*129)
#define HIN 33

typedef unsigned long long u64;

__device__ __forceinline__ u64 fma2(u64 a, u64 b, u64 c) {
    u64 d;
    asm("fma.rn.f32x2 %0, %1, %2, %3;" : "=l"(d) : "l"(a), "l"(b), "l"(c));
    return d;
}
__device__ __forceinline__ u64 pack2(float lo, float hi) {
    u64 d;
    asm("mov.b64 %0, {%1, %2};" : "=l"(d) : "f"(lo), "f"(hi));
    return d;
}
__device__ __forceinline__ float2 unpack2(u64 v) {
    float2 r;
    asm("mov.b64 {%0, %1}, %2;" : "=f"(r.x), "=f"(r.y) : "l"(v));
    return r;
}

// scratch (allocation-free rule: __device__ globals)
__device__ float g_cur_up[2*128*HWc];
__device__ float g_key_up[2*128*HWc];
__device__ float g_concat[2*512*HWc];
__device__ float g_x2[2*256*HWc];
__device__ float g_kern[2*49*HWc];
__device__ float g_wrT[128*9*256];
__device__ float g_w2T[512*9*256];

// ---------------------------------------------------------------- upsample --
__global__ void upsample_kernel(const float* __restrict__ in,
                                float* __restrict__ out, int total)
{
    int idx = blockIdx.x * blockDim.x + threadIdx.x;
    if (idx >= total) return;
    int pix = idx % HWc;
    int nc  = idx / HWc;
    int y = pix / Wc, x = pix % Wc;
    const float s = 33.0f / 129.0f;
    float sy = (y + 0.5f) * s - 0.5f;
    float sx = (x + 0.5f) * s - 0.5f;
    float fy = floorf(sy), fx = floorf(sx);
    int y0 = (int)fy, x0 = (int)fx;
    float wy = sy - fy, wx = sx - fx;
    int y0c = max(y0, 0), y1c = min(y0 + 1, HIN - 1);
    int x0c = max(x0, 0), x1c = min(x0 + 1, HIN - 1);
    const float* p = in + nc * (HIN * HIN);
    float v00 = p[y0c * HIN + x0c];
    float v01 = p[y0c * HIN + x1c];
    float v10 = p[y1c * HIN + x0c];
    float v11 = p[y1c * HIN + x1c];
    float v0 = v00 + (v01 - v00) * wx;
    float v1 = v10 + (v11 - v10) * wx;
    out[idx] = v0 + (v1 - v0) * wy;
}

// --------------------------------------------------- weight pre-transpose  --
__global__ void transpose_w_kernel(const float* __restrict__ in,
                                   float* __restrict__ out, int OC, int R)
{
    __shared__ float tile[32][33];
    int xc = blockIdx.x * 32 + threadIdx.x;
    int yr = blockIdx.y * 32 + threadIdx.y;
#pragma unroll
    for (int j = 0; j < 32; j += 8) {
        int oc = yr + j;
        if (oc < OC && xc < R)
            tile[threadIdx.y + j][threadIdx.x] = in[oc * R + xc];
    }
    __syncthreads();
    int oc = blockIdx.y * 32 + threadIdx.x;
    int r0 = blockIdx.x * 32 + threadIdx.y;
#pragma unroll
    for (int j = 0; j < 32; j += 8) {
        int r = r0 + j;
        if (r < R && oc < OC)
            out[r * OC + oc] = tile[threadIdx.x][threadIdx.y + j];
    }
}

// ------------------------------------------------------------- 3x3 conv    --
// Block: 128 oc x (8 rows x 16 cols) px, 256 threads. Thread: 8 oc x 8 px.
// f32x2 pairs over adjacent output channels; weights via LDS.128.
template<int CIN>
__global__ __launch_bounds__(256)
void conv3x3_relu_kernel(const float* __restrict__ in,
                         const float* __restrict__ wT,   // [(ic*9+k)*256 + oc]
                         const float* __restrict__ bias,
                         float* __restrict__ out,
                         int in_img_stride, int out_img_stride)
{
    constexpr int ICS = 4;
    constexpr int PITCH = 19;
    __shared__ float s_in[2][ICS][10 * PITCH];
    __shared__ __align__(16) float s_w[2][ICS][9][128];

    const int tid = threadIdx.x;
    const int tx0 = blockIdx.x * 16;
    const int ty0 = blockIdx.y * 8;
    const int n   = blockIdx.z >> 1;
    const int ocb = blockIdx.z & 1;
    const float* inb = in + n * in_img_stride;
    float* outb = out + n * out_img_stride + (ocb * 128) * HWc;
    const int oc_g = ocb * 128;

    const int tid_oc = tid >> 4;            // 0..15
    const int tid_px = tid & 15;            // 0..15
    const int oc0 = tid_oc * 8;             // 8 oc per thread
    const int row = tid_px >> 1;            // 0..7
    const int col0 = (tid_px & 1) * 8;      // 0 or 8

    u64 acc2[4][8];                          // [oc-pair][pixel]
#pragma unroll
    for (int o = 0; o < 4; o++)
#pragma unroll
        for (int p = 0; p < 8; p++) acc2[o][p] = 0ull;

    const int NSTAGE = CIN / ICS;
    for (int s = 0; s < NSTAGE; s++) {
        const int buf = s & 1;
        const int ic0 = s * ICS;
        // input patch: ICS x 10 x 18
        for (int idx = tid; idx < ICS * 10 * 18; idx += 256) {
            int icl = idx / 180;
            int r   = (idx / 18) % 10;
            int c   = idx % 18;
            int gy = ty0 - 1 + r, gx = tx0 - 1 + c;
            float v = 0.f;
            if ((unsigned)gy < Hc && (unsigned)gx < Wc)
                v = inb[(ic0 + icl) * HWc + gy * Wc + gx];
            s_in[buf][icl][r * PITCH + c] = v;
        }
        // weights: ICS x 9 x 128 (coalesced)
        for (int idx = tid; idx < ICS * 9 * 128; idx += 256) {
            int icl = idx / (9 * 128);
            int k   = (idx / 128) % 9;
            int ocl = idx % 128;
            s_w[buf][icl][k][ocl] = wT[((ic0 + icl) * 9 + k) * 256 + oc_g + ocl];
        }
        __syncthreads();
#pragma unroll
        for (int icl = 0; icl < ICS; icl++) {
#pragma unroll
            for (int kh = 0; kh < 3; kh++) {
                float ir[10];
#pragma unroll
                for (int i = 0; i < 10; i++)
                    ir[i] = s_in[buf][icl][(row + kh) * PITCH + col0 + i];
                u64 dup[10];
#pragma unroll
                for (int i = 0; i < 10; i++) dup[i] = pack2(ir[i], ir[i]);
#pragma unroll
                for (int kw = 0; kw < 3; kw++) {
                    const float4* wp = (const float4*)&s_w[buf][icl][kh * 3 + kw][oc0];
                    float4 wa = wp[0];
                    float4 wb = wp[1];
                    u64 w01 = pack2(wa.x, wa.y);
                    u64 w23 = pack2(wa.z, wa.w);
                    u64 w45 = pack2(wb.x, wb.y);
                    u64 w67 = pack2(wb.z, wb.w);
#pragma unroll
                    for (int p = 0; p < 8; p++) {
                        u64 iv = dup[p + kw];
                        acc2[0][p] = fma2(w01, iv, acc2[0][p]);
                        acc2[1][p] = fma2(w23, iv, acc2[1][p]);
                        acc2[2][p] = fma2(w45, iv, acc2[2][p]);
                        acc2[3][p] = fma2(w67, iv, acc2[3][p]);
                    }
                }
            }
        }
    }
    float b[8];
#pragma unroll
    for (int o = 0; o < 8; o++) b[o] = bias[oc_g + oc0 + o];

    const int y = ty0 + row;
#pragma unroll
    for (int o = 0; o < 4; o++) {
#pragma unroll
        for (int p = 0; p < 8; p++) {
            int x = tx0 + col0 + p;
            if (y < Hc && x < Wc) {
                float2 v = unpack2(acc2[o][p]);
                outb[(oc0 + 2 * o)     * HWc + y * Wc + x] = fmaxf(v.x + b[2 * o],     0.f);
                outb[(oc0 + 2 * o + 1) * HWc + y * Wc + x] = fmaxf(v.y + b[2 * o + 1], 0.f);
            }
        }
    }
}

// --------------------------------------------- 1x1 conv + relu + softmax   --
__global__ __launch_bounds__(256)
void conv3_softmax_kernel(const float* __restrict__ x,
                          const float* __restrict__ w3,   // (49,256)
                          const float* __restrict__ b3,
                          float* __restrict__ kout)
{
    extern __shared__ float ws[];           // [c*50 + oc]
    for (int idx = threadIdx.x; idx < 256 * 50; idx += 256) {
        int c = idx / 50, oc = idx % 50;
        ws[idx] = (oc < 49) ? w3[oc * 256 + c] : 0.f;
    }
    __syncthreads();

    int p = blockIdx.x * 256 + threadIdx.x;
    if (p >= 2 * HWc) return;
    int n = p / HWc, pix = p % HWc;
    const float* xb = x + n * 256 * HWc + pix;

    u64 acc2[24];
#pragma unroll
    for (int q = 0; q < 24; q++) acc2[q] = 0ull;
    float acc48 = 0.f;

#pragma unroll 4
    for (int c = 0; c < 256; c++) {
        float xv = xb[c * HWc];
        u64 xd = pack2(xv, xv);
        const u64* wr = (const u64*)&ws[c * 50];
#pragma unroll
        for (int q = 0; q < 24; q++) acc2[q] = fma2(wr[q], xd, acc2[q]);
        acc48 += xv * ws[c * 50 + 48];
    }

    float a[49];
#pragma unroll
    for (int q = 0; q < 24; q++) {
        float2 v = unpack2(acc2[q]);
        a[2 * q] = v.x; a[2 * q + 1] = v.y;
    }
    a[48] = acc48;

    float m = -1e30f;
#pragma unroll
    for (int oc = 0; oc < 49; oc++) {
        a[oc] = fmaxf(a[oc] + b3[oc], 0.f);
        m = fmaxf(m, a[oc]);
    }
    float ssum = 0.f;
#pragma unroll
    for (int oc = 0; oc < 49; oc++) {
        a[oc] = __expf(a[oc] - m);
        ssum += a[oc];
    }
    float inv = 1.f / ssum;
    float* kb = kout + n * 49 * HWc + pix;
#pragma unroll
    for (int oc = 0; oc < 49; oc++) kb[oc * HWc] = a[oc] * inv;
}

// --------------------------------------------- spatially-variant 7x7 conv  --
__global__ __launch_bounds__(256)
void svconv_kernel(const float* __restrict__ feat,
                   const float* __restrict__ kern,
                   float* __restrict__ out)
{
    constexpr int TS = 16, PAD = 3, FT = TS + 2 * PAD;   // 22
    __shared__ float sf[2][FT * FT];

    const int tid = threadIdx.x;
    const int txi = tid & 15, tyi = tid >> 4;
    const int bx = blockIdx.x * TS, by = blockIdx.y * TS;
    const int n = blockIdx.z >> 2;
    const int c0 = (blockIdx.z & 3) * 64;
    const int x = bx + txi, y = by + tyi;
    const bool valid = (x < Wc) && (y < Hc);

    float kv[49];
    if (valid) {
        const float* kb = kern + n * 49 * HWc + y * Wc + x;
#pragma unroll
        for (int t = 0; t < 49; t++) kv[t] = kb[t * HWc];
    } else {
#pragma unroll
        for (int t = 0; t < 49; t++) kv[t] = 0.f;
    }

    const float* fb = feat + (n * 256 + c0) * HWc;
    float* ob = out + (n * 256 + c0) * HWc;

    for (int cl = 0; cl < 64; cl++) {
        const int buf = cl & 1;
        const float* fc = fb + cl * HWc;
        for (int idx = tid; idx < FT * FT; idx += 256) {
            int r = idx / FT, cc = idx % FT;
            int gy = by - PAD + r, gx = bx - PAD + cc;
            float v = 0.f;
            if ((unsigned)gy < Hc && (unsigned)gx < Wc) v = fc[gy * Wc + gx];
            sf[buf][idx] = v;
        }
        __syncthreads();
        if (valid) {
            float a = 0.f;
#pragma unroll
            for (int i = 0; i < 7; i++)
#pragma unroll
                for (int j = 0; j < 7; j++)
                    a += kv[i * 7 + j] * sf[buf][(tyi + i) * FT + txi + j];
            ob[cl * HWc + y * Wc + x] = a;
        }
    }
}

// ---------------------------------------------------------------------------
extern "C" void kernel_launch(void* const* d_in, const int* in_sizes, int n_in,
                              void* d_out, int out_size)
{
    const float* cur_low  = (const float*)d_in[0];
    const float* key_low  = (const float*)d_in[1];
    const float* key_high = (const float*)d_in[2];
    const float* w_reduce = (const float*)d_in[3];
    const float* b_reduce = (const float*)d_in[4];
    const float* w_conv2  = (const float*)d_in[5];
    const float* b_conv2  = (const float*)d_in[6];
    const float* w_conv3  = (const float*)d_in[7];
    const float* b_conv3  = (const float*)d_in[8];
    float* out = (float*)d_out;

    float *cur_up, *key_up, *concat, *x2, *kern, *wrT, *w2T;
    cudaGetSymbolAddress((void**)&cur_up, g_cur_up);
    cudaGetSymbolAddress((void**)&key_up, g_key_up);
    cudaGetSymbolAddress((void**)&concat, g_concat);
    cudaGetSymbolAddress((void**)&x2, g_x2);
    cudaGetSymbolAddress((void**)&kern, g_kern);
    cudaGetSymbolAddress((void**)&wrT, g_wrT);
    cudaGetSymbolAddress((void**)&w2T, g_w2T);

    // weight pre-transpose (tiled)
    {
        dim3 blk(32, 8);
        dim3 g1((128 * 9 + 31) / 32, (256 + 31) / 32);
        transpose_w_kernel<<<g1, blk>>>(w_reduce, wrT, 256, 128 * 9);
        dim3 g2((512 * 9 + 31) / 32, (256 + 31) / 32);
        transpose_w_kernel<<<g2, blk>>>(w_conv2, w2T, 256, 512 * 9);
    }
    // upsample both low-feature tensors
    {
        int total = 2 * 128 * HWc;
        upsample_kernel<<<(total + 255) / 256, 256>>>(cur_low, cur_up, total);
        upsample_kernel<<<(total + 255) / 256, 256>>>(key_low, key_up, total);
    }
    // conv_reduce (shared weights), writing directly into concat layout
    {
        dim3 grid(9, 17, 4);   // z = n(2) * ocb(2)
        conv3x3_relu_kernel<128><<<grid, 256>>>(
            cur_up, wrT, b_reduce, concat, 128 * HWc, 512 * HWc);
        conv3x3_relu_kernel<128><<<grid, 256>>>(
            key_up, wrT, b_reduce, concat + 256 * HWc, 128 * HWc, 512 * HWc);
    }
    // conv2: 512 -> 256
    {
        dim3 grid(9, 17, 4);
        conv3x3_relu_kernel<512><<<grid, 256>>>(
            concat, w2T, b_conv2, x2, 512 * HWc, 256 * HWc);
    }
    // conv3 (1x1, 256->49) + relu + softmax
    {
        int smem = 256 * 50 * sizeof(float);
        cudaFuncSetAttribute(conv3_softmax_kernel,
                             cudaFuncAttributeMaxDynamicSharedMemorySize, smem);
        int total = 2 * HWc;
        conv3_softmax_kernel<<<(total + 255) / 256, 256, smem>>>(
            x2, w_conv3, b_conv3, kern);
    }
    // spatially-variant 7x7 conv
    {
        dim3 grid(9, 9, 8);
        svconv_kernel<<<grid, 256>>>(key_high, kern, out);
    }
}

// round 12
// speedup vs baseline: 1.9891x; 1.9891x over previous
#include <cuda_runtime.h>
#include <cuda_bf16.h>
#include <math.h>
#include <stdint.h>

// ----------------------------------------------------------------------------
// AdaptiveFeaturePropagation — mma.sync (HMMA) bf16 split-precision GEMM
//
//  conv3x3(X, W) == shiftsum_tap( G ),
//  G[tap*256+oc, p] = sum_ic W[oc,ic,tap] * Xpad[ic,p]
//  over padded 131x131 pixel domain (zero borders), NHWC activations.
// ----------------------------------------------------------------------------

#define Hc   129
#define Wc   129
#define HWc  (129*129)      // 16641
#define HIN  33
#define PW   131
#define NP   (131*131)      // 17161  padded pixel count
#define MTOT 2304           // 9 taps * 256 oc

typedef unsigned long long u64;

// ------------------------------------------------------------ ptx helpers --
__device__ __forceinline__ uint32_t smem_to_u32(const void* p) {
    uint32_t a;
    asm("{ .reg .u64 t; cvta.to.shared.u64 t, %1; cvt.u32.u64 %0, t; }"
        : "=r"(a) : "l"(p));
    return a;
}

#define LDSM_X4(r0, r1, r2, r3, addr) \
    asm volatile("ldmatrix.sync.aligned.m8n8.x4.shared.b16 {%0,%1,%2,%3}, [%4];" \
                 : "=r"(r0), "=r"(r1), "=r"(r2), "=r"(r3) : "r"(addr))

#define MMA_BF16(d, a, b) \
    asm volatile("mma.sync.aligned.m16n8k16.row.col.f32.bf16.bf16.f32 " \
                 "{%0,%1,%2,%3}, {%4,%5,%6,%7}, {%8,%9}, {%0,%1,%2,%3};" \
                 : "+f"((d)[0]), "+f"((d)[1]), "+f"((d)[2]), "+f"((d)[3]) \
                 : "r"((a)[0]), "r"((a)[1]), "r"((a)[2]), "r"((a)[3]), \
                   "r"((b)[0]), "r"((b)[1]))

// ------------------------------------------------------------- scratch ----
__device__ __nv_bfloat16 g_Xt1_hi[4ll * NP * 128];   // upsampled low feats, NHWC padded
__device__ __nv_bfloat16 g_Xt1_lo[4ll * NP * 128];
__device__ __nv_bfloat16 g_Xt2_hi[2ll * NP * 512];   // concat(reduce outputs), NHWC padded
__device__ __nv_bfloat16 g_Xt2_lo[2ll * NP * 512];
__device__ __nv_bfloat16 g_A1_hi[MTOT * 128];        // w_reduce  [tap*256+oc][ic]
__device__ __nv_bfloat16 g_A1_lo[MTOT * 128];
__device__ __nv_bfloat16 g_A2_hi[MTOT * 512];        // w_conv2   [tap*256+oc][ic]
__device__ __nv_bfloat16 g_A2_lo[MTOT * 512];
__device__ float g_G[(long long)MTOT * NP];          // GEMM output (reused per frame)
__device__ float g_x2[2ll * 256 * HWc];              // conv2 output (std layout)
__device__ float g_kern[2ll * 49 * HWc];             // softmax kernels

__device__ __forceinline__ void bf16_split(float v, __nv_bfloat16& hi, __nv_bfloat16& lo) {
    hi = __float2bfloat16(v);
    lo = __float2bfloat16(v - __bfloat162float(hi));
}

// ------------------------------------------- weight prep (hi/lo, re-order) --
__global__ void prep_w_kernel(const float* __restrict__ w, int CIN,
                              __nv_bfloat16* __restrict__ Ah,
                              __nv_bfloat16* __restrict__ Al)
{
    long long idx = (long long)blockIdx.x * blockDim.x + threadIdx.x;
    long long total = (long long)MTOT * CIN;
    if (idx >= total) return;
    int m  = (int)(idx / CIN);
    int ic = (int)(idx % CIN);
    int tap = m / 256, oc = m % 256;
    float v = w[((long long)oc * CIN + ic) * 9 + tap];
    __nv_bfloat16 h, l; bf16_split(v, h, l);
    Ah[idx] = h; Al[idx] = l;
}

// ---------------------------------------- upsample + split into NHWC pad ---
// grid (HWc, 4 frames), block 128 (= ic). frames 0,1 = cur imgs, 2,3 = key.
__global__ void upsample_split_kernel(const float* __restrict__ cur_low,
                                      const float* __restrict__ key_low,
                                      __nv_bfloat16* __restrict__ Xh,
                                      __nv_bfloat16* __restrict__ Xl)
{
    int pix = blockIdx.x;
    int f   = blockIdx.y;
    int ic  = threadIdx.x;
    int y = pix / Wc, x = pix % Wc;
    const float s = 33.0f / 129.0f;
    float sy = (y + 0.5f) * s - 0.5f;
    float sx = (x + 0.5f) * s - 0.5f;
    float fy = floorf(sy), fx = floorf(sx);
    int y0 = (int)fy, x0 = (int)fx;
    float wy = sy - fy, wx = sx - fx;
    int y0c = max(y0, 0), y1c = min(y0 + 1, HIN - 1);
    int x0c = max(x0, 0), x1c = min(x0 + 1, HIN - 1);
    const float* src = (f < 2) ? (cur_low + ((long long)f * 128 + ic) * (HIN * HIN))
                               : (key_low + ((long long)(f - 2) * 128 + ic) * (HIN * HIN));
    float v00 = src[y0c * HIN + x0c];
    float v01 = src[y0c * HIN + x1c];
    float v10 = src[y1c * HIN + x0c];
    float v11 = src[y1c * HIN + x1c];
    float v0 = v00 + (v01 - v00) * wx;
    float v1 = v10 + (v11 - v10) * wx;
    float v  = v0 + (v1 - v0) * wy;
    int ppad = (y + 1) * PW + (x + 1);
    long long o = ((long long)f * NP + ppad) * 128 + ic;
    __nv_bfloat16 h, l; bf16_split(v, h, l);
    Xh[o] = h; Xl[o] = l;
}

// ------------------------------------------------------- HMMA GEMM --------
// D[m, p] = sum_k (Ahi+Alo)[m,k] * (Bhi+Blo)[p,k]  (3-term split, fp32 accum)
// Block: 256 thr. Tile M=128, N=128, K-slab 64. Warp (2x4): 64x32.
static constexpr int SA_HI = 0;
static constexpr int SA_LO = 16384;
static constexpr int SBm_HI = 32768;
static constexpr int SBm_LO = 49152;
static constexpr int SMEM_GEMM = 65536;

template<int K>
__global__ __launch_bounds__(256, 1)
void gemm_mma_kernel(const __nv_bfloat16* __restrict__ A_hi,
                     const __nv_bfloat16* __restrict__ A_lo,
                     const __nv_bfloat16* __restrict__ B_hi,
                     const __nv_bfloat16* __restrict__ B_lo,
                     float* __restrict__ G)
{
    extern __shared__ char smem[];
    const uint32_t sb = smem_to_u32(smem);
    const int tid  = threadIdx.x;
    const int wid  = tid >> 5;
    const int lane = tid & 31;
    const int wm = wid >> 2;            // 0..1  (M warp)
    const int wn = wid & 3;             // 0..3  (N warp)
    const int mt_blk = blockIdx.y;
    const int p0 = blockIdx.x * 128;

    float acc[4][4][4];
#pragma unroll
    for (int mi = 0; mi < 4; mi++)
#pragma unroll
        for (int ni = 0; ni < 4; ni++)
#pragma unroll
            for (int r = 0; r < 4; r++) acc[mi][ni][r] = 0.f;

    // per-lane ldmatrix address components
    // A: lanes 0-15 -> rows m0-15 @k0 ; lanes 16-31 -> rows m0-15 @k+8
    const int a_row_l = wm * 64 + (lane & 15);
    const int a_kb_l  = (lane >> 4) * 16;
    // B: lanes (0-7, 8-15, 16-23, 24-31) -> (n0-7@k0, n0-7@k8, n8-15@k0, n8-15@k8)
    const int b_row_l = wn * 32 + (lane & 7) + ((lane >> 4) & 1) * 8;
    const int b_kb_l  = ((lane >> 3) & 1) * 16;

    const int NS = K / 64;
    for (int s = 0; s < NS; s++) {
        const int k0 = s * 64;
        // ---- fill A tiles (128 x 64 bf16, 128B rows, SW128 swizzle) ----
#pragma unroll
        for (int i = tid; i < 1024; i += 256) {
            int r = i >> 3, q = i & 7;
            long long ga = (long long)(mt_blk * 128 + r) * K + k0 + q * 8;
            uint32_t off = (uint32_t)(r * 128 + ((q * 16) ^ ((r & 7) << 4)));
            *(uint4*)(smem + SA_HI + off) = *(const uint4*)(A_hi + ga);
            *(uint4*)(smem + SA_LO + off) = *(const uint4*)(A_lo + ga);
        }
        // ---- fill B tiles (128 px rows x 64 bf16) ----
#pragma unroll
        for (int i = tid; i < 1024; i += 256) {
            int r = i >> 3, q = i & 7;
            int p = p0 + r;
            uint4 vh = make_uint4(0, 0, 0, 0);
            uint4 vl = make_uint4(0, 0, 0, 0);
            if (p < NP) {
                long long gb = (long long)p * K + k0 + q * 8;
                vh = *(const uint4*)(B_hi + gb);
                vl = *(const uint4*)(B_lo + gb);
            }
            uint32_t off = (uint32_t)(r * 128 + ((q * 16) ^ ((r & 7) << 4)));
            *(uint4*)(smem + SBm_HI + off) = vh;
            *(uint4*)(smem + SBm_LO + off) = vl;
        }
        __syncthreads();

#pragma unroll
        for (int ks = 0; ks < 4; ks++) {
            const int kbase = ks * 32;
            uint32_t a[4][4], b_hi[4][2], b_lo[4][2];
            // A hi fragments (4 m16 tiles)
#pragma unroll
            for (int mi = 0; mi < 4; mi++) {
                int row = a_row_l + mi * 16;
                uint32_t ad = sb + SA_HI + row * 128
                            + (((kbase + a_kb_l)) ^ ((row & 7) << 4));
                LDSM_X4(a[mi][0], a[mi][1], a[mi][2], a[mi][3], ad);
            }
            // B hi / lo fragments (2 ldmatrix.x4 each -> 4 n8 frags)
#pragma unroll
            for (int bt = 0; bt < 2; bt++) {
                int row = b_row_l + bt * 16;
                uint32_t xm = (uint32_t)((row & 7) << 4);
                uint32_t adh = sb + SBm_HI + row * 128 + ((kbase + b_kb_l) ^ xm);
                uint32_t adl = sb + SBm_LO + row * 128 + ((kbase + b_kb_l) ^ xm);
                LDSM_X4(b_hi[2 * bt][0], b_hi[2 * bt][1],
                        b_hi[2 * bt + 1][0], b_hi[2 * bt + 1][1], adh);
                LDSM_X4(b_lo[2 * bt][0], b_lo[2 * bt][1],
                        b_lo[2 * bt + 1][0], b_lo[2 * bt + 1][1], adl);
            }
            // chain 1: Ahi * Bhi   chain 2: Ahi * Blo
#pragma unroll
            for (int mi = 0; mi < 4; mi++)
#pragma unroll
                for (int ni = 0; ni < 4; ni++) {
                    MMA_BF16(acc[mi][ni], a[mi], b_hi[ni]);
                    MMA_BF16(acc[mi][ni], a[mi], b_lo[ni]);
                }
            // chain 3: Alo * Bhi  (reload A regs with lo)
#pragma unroll
            for (int mi = 0; mi < 4; mi++) {
                int row = a_row_l + mi * 16;
                uint32_t ad = sb + SA_LO + row * 128
                            + (((kbase + a_kb_l)) ^ ((row & 7) << 4));
                LDSM_X4(a[mi][0], a[mi][1], a[mi][2], a[mi][3], ad);
            }
#pragma unroll
            for (int mi = 0; mi < 4; mi++)
#pragma unroll
                for (int ni = 0; ni < 4; ni++)
                    MMA_BF16(acc[mi][ni], a[mi], b_hi[ni]);
        }
        __syncthreads();
    }

    // ---- epilogue: accum fragments -> G[m][p] ----
    const int m_base = mt_blk * 128 + wm * 64 + (lane >> 2);
    const int p_base = p0 + wn * 32 + (lane & 3) * 2;
#pragma unroll
    for (int mi = 0; mi < 4; mi++) {
#pragma unroll
        for (int ni = 0; ni < 4; ni++) {
            int m = m_base + mi * 16;
            int p = p_base + ni * 8;
            float* g0 = G + (long long)m * NP;
            float* g1 = g0 + 8ll * NP;
            if (p < NP)     { g0[p] = acc[mi][ni][0]; g1[p] = acc[mi][ni][2]; }
            if (p + 1 < NP) { g0[p + 1] = acc[mi][ni][1]; g1[p + 1] = acc[mi][ni][3]; }
        }
    }
}

// --------------------------------- shifted tap-sum epilogues ---------------
// conv_reduce: G -> relu(+bias) -> bf16 hi/lo into Xt2 (NHWC padded, concat ch)
__global__ __launch_bounds__(256)
void shiftsum_reduce_kernel(const float* __restrict__ G,
                            const float* __restrict__ bias,
                            __nv_bfloat16* __restrict__ Xh,
                            __nv_bfloat16* __restrict__ Xl,
                            int img, int cbase)
{
    __shared__ float t[64][65];
    const int tid = threadIdx.x;
    const int x0  = blockIdx.x * 64;
    const int y   = blockIdx.y;
    const int oc0 = blockIdx.z * 64;

#pragma unroll 1
    for (int it = 0; it < 16; it++) {
        int idx = it * 256 + tid;
        int ocl = idx >> 6, px = idx & 63;
        int xx = x0 + px;
        float v = 0.f;
        if (xx < Wc) {
            int oc = oc0 + ocl;
            v = bias[oc];
#pragma unroll
            for (int kh = 0; kh < 3; kh++)
#pragma unroll
                for (int kw = 0; kw < 3; kw++) {
                    int tap = kh * 3 + kw;
                    v += G[(long long)(tap * 256 + oc) * NP + (y + kh) * PW + xx + kw];
                }
            v = fmaxf(v, 0.f);
        }
        t[ocl][px] = v;
    }
    __syncthreads();
#pragma unroll 1
    for (int it = 0; it < 16; it++) {
        int idx = it * 256 + tid;
        int px = idx >> 6, ocl = idx & 63;
        int xx = x0 + px;
        if (xx < Wc) {
            int ppad = (y + 1) * PW + xx + 1;
            long long o = ((long long)img * NP + ppad) * 512 + cbase + oc0 + ocl;
            float v = t[ocl][px];
            __nv_bfloat16 h, l; bf16_split(v, h, l);
            Xh[o] = h; Xl[o] = l;
        }
    }
}

// conv2: G -> relu(+bias) -> fp32 x2 (standard [oc][HW] layout)
__global__ __launch_bounds__(256)
void shiftsum_conv2_kernel(const float* __restrict__ G,
                           const float* __restrict__ bias,
                           float* __restrict__ x2img)
{
    int oc  = blockIdx.y;
    int pix = blockIdx.x * 256 + threadIdx.x;
    if (pix >= HWc) return;
    int y = pix / Wc, x = pix % Wc;
    float v = bias[oc];
#pragma unroll
    for (int kh = 0; kh < 3; kh++)
#pragma unroll
        for (int kw = 0; kw < 3; kw++) {
            int tap = kh * 3 + kw;
            v += G[(long long)(tap * 256 + oc) * NP + (y + kh) * PW + x + kw];
        }
    x2img[(long long)oc * HWc + pix] = fmaxf(v, 0.f);
}

// --------------------------------------------- 1x1 conv + relu + softmax   --
__device__ __forceinline__ u64 fma2(u64 a, u64 b, u64 c) {
    u64 d;
    asm("fma.rn.f32x2 %0, %1, %2, %3;" : "=l"(d) : "l"(a), "l"(b), "l"(c));
    return d;
}
__device__ __forceinline__ u64 pack2(float lo, float hi) {
    u64 d;
    asm("mov.b64 %0, {%1, %2};" : "=l"(d) : "f"(lo), "f"(hi));
    return d;
}
__device__ __forceinline__ float2 unpack2(u64 v) {
    float2 r;
    asm("mov.b64 {%0, %1}, %2;" : "=f"(r.x), "=f"(r.y) : "l"(v));
    return r;
}

__global__ __launch_bounds__(256)
void conv3_softmax_kernel(const float* __restrict__ x,
                          const float* __restrict__ w3,   // (49,256)
                          const float* __restrict__ b3,
                          float* __restrict__ kout)
{
    extern __shared__ float ws[];           // [c*50 + oc]
    for (int idx = threadIdx.x; idx < 256 * 50; idx += 256) {
        int c = idx / 50, oc = idx % 50;
        ws[idx] = (oc < 49) ? w3[oc * 256 + c] : 0.f;
    }
    __syncthreads();

    int p = blockIdx.x * 256 + threadIdx.x;
    if (p >= 2 * HWc) return;
    int n = p / HWc, pix = p % HWc;
    const float* xb = x + (long long)n * 256 * HWc + pix;

    u64 acc2[24];
#pragma unroll
    for (int q = 0; q < 24; q++) acc2[q] = 0ull;
    float acc48 = 0.f;

#pragma unroll 4
    for (int c = 0; c < 256; c++) {
        float xv = xb[(long long)c * HWc];
        u64 xd = pack2(xv, xv);
        const u64* wr = (const u64*)&ws[c * 50];
#pragma unroll
        for (int q = 0; q < 24; q++) acc2[q] = fma2(wr[q], xd, acc2[q]);
        acc48 += xv * ws[c * 50 + 48];
    }

    float a[49];
#pragma unroll
    for (int q = 0; q < 24; q++) {
        float2 v = unpack2(acc2[q]);
        a[2 * q] = v.x; a[2 * q + 1] = v.y;
    }
    a[48] = acc48;

    float m = -1e30f;
#pragma unroll
    for (int oc = 0; oc < 49; oc++) {
        a[oc] = fmaxf(a[oc] + b3[oc], 0.f);
        m = fmaxf(m, a[oc]);
    }
    float ssum = 0.f;
#pragma unroll
    for (int oc = 0; oc < 49; oc++) {
        a[oc] = __expf(a[oc] - m);
        ssum += a[oc];
    }
    float inv = 1.f / ssum;
    float* kb = kout + (long long)n * 49 * HWc + pix;
#pragma unroll
    for (int oc = 0; oc < 49; oc++) kb[(long long)oc * HWc] = a[oc] * inv;
}

// --------------------------------------------- spatially-variant 7x7 conv  --
__global__ __launch_bounds__(256)
void svconv_kernel(const float* __restrict__ feat,
                   const float* __restrict__ kern,
                   float* __restrict__ out)
{
    constexpr int TS = 16, PAD = 3, FT = TS + 2 * PAD;   // 22
    __shared__ float sf[2][FT * FT];

    const int tid = threadIdx.x;
    const int txi = tid & 15, tyi = tid >> 4;
    const int bx = blockIdx.x * TS, by = blockIdx.y * TS;
    const int n = blockIdx.z >> 2;
    const int c0 = (blockIdx.z & 3) * 64;
    const int x = bx + txi, y = by + tyi;
    const bool valid = (x < Wc) && (y < Hc);

    float kv[49];
    if (valid) {
        const float* kb = kern + (long long)n * 49 * HWc + y * Wc + x;
#pragma unroll
        for (int t = 0; t < 49; t++) kv[t] = kb[(long long)t * HWc];
    } else {
#pragma unroll
        for (int t = 0; t < 49; t++) kv[t] = 0.f;
    }

    const float* fb = feat + ((long long)n * 256 + c0) * HWc;
    float* ob = out + ((long long)n * 256 + c0) * HWc;

    for (int cl = 0; cl < 64; cl++) {
        const int buf = cl & 1;
        const float* fc = fb + (long long)cl * HWc;
        for (int idx = tid; idx < FT * FT; idx += 256) {
            int r = idx / FT, cc = idx % FT;
            int gy = by - PAD + r, gx = bx - PAD + cc;
            float v = 0.f;
            if ((unsigned)gy < Hc && (unsigned)gx < Wc) v = fc[gy * Wc + gx];
            sf[buf][idx] = v;
        }
        __syncthreads();
        if (valid) {
            float a = 0.f;
#pragma unroll
            for (int i = 0; i < 7; i++)
#pragma unroll
                for (int j = 0; j < 7; j++)
                    a += kv[i * 7 + j] * sf[buf][(tyi + i) * FT + txi + j];
            ob[(long long)cl * HWc + y * Wc + x] = a;
        }
    }
}

// ---------------------------------------------------------------------------
extern "C" void kernel_launch(void* const* d_in, const int* in_sizes, int n_in,
                              void* d_out, int out_size)
{
    const float* cur_low  = (const float*)d_in[0];
    const float* key_low  = (const float*)d_in[1];
    const float* key_high = (const float*)d_in[2];
    const float* w_reduce = (const float*)d_in[3];
    const float* b_reduce = (const float*)d_in[4];
    const float* w_conv2  = (const float*)d_in[5];
    const float* b_conv2  = (const float*)d_in[6];
    const float* w_conv3  = (const float*)d_in[7];
    const float* b_conv3  = (const float*)d_in[8];
    float* out = (float*)d_out;

    __nv_bfloat16 *Xt1h, *Xt1l, *Xt2h, *Xt2l, *A1h, *A1l, *A2h, *A2l;
    float *G, *x2, *kern;
    cudaGetSymbolAddress((void**)&Xt1h, g_Xt1_hi);
    cudaGetSymbolAddress((void**)&Xt1l, g_Xt1_lo);
    cudaGetSymbolAddress((void**)&Xt2h, g_Xt2_hi);
    cudaGetSymbolAddress((void**)&Xt2l, g_Xt2_lo);
    cudaGetSymbolAddress((void**)&A1h, g_A1_hi);
    cudaGetSymbolAddress((void**)&A1l, g_A1_lo);
    cudaGetSymbolAddress((void**)&A2h, g_A2_hi);
    cudaGetSymbolAddress((void**)&A2l, g_A2_lo);
    cudaGetSymbolAddress((void**)&G, g_G);
    cudaGetSymbolAddress((void**)&x2, g_x2);
    cudaGetSymbolAddress((void**)&kern, g_kern);

    cudaFuncSetAttribute(gemm_mma_kernel<128>,
                         cudaFuncAttributeMaxDynamicSharedMemorySize, SMEM_GEMM);
    cudaFuncSetAttribute(gemm_mma_kernel<512>,
                         cudaFuncAttributeMaxDynamicSharedMemorySize, SMEM_GEMM);

    // weight prep
    {
        long long t1 = (long long)MTOT * 128;
        prep_w_kernel<<<(unsigned)((t1 + 255) / 256), 256>>>(w_reduce, 128, A1h, A1l);
        long long t2 = (long long)MTOT * 512;
        prep_w_kernel<<<(unsigned)((t2 + 255) / 256), 256>>>(w_conv2, 512, A2h, A2l);
    }
    // upsample + split into NHWC padded
    {
        dim3 grid(HWc, 4);
        upsample_split_kernel<<<grid, 128>>>(cur_low, key_low, Xt1h, Xt1l);
    }
    // conv_reduce via GEMM + shiftsum, 4 frames (cur img0/1, key img0/1)
    for (int f = 0; f < 4; f++) {
        dim3 ggrid((NP + 127) / 128, MTOT / 128);    // (135, 18)
        gemm_mma_kernel<128><<<ggrid, 256, SMEM_GEMM>>>(
            A1h, A1l,
            Xt1h + (long long)f * NP * 128,
            Xt1l + (long long)f * NP * 128, G);
        dim3 sgrid((Wc + 63) / 64, Hc, 4);           // (3, 129, 4)
        shiftsum_reduce_kernel<<<sgrid, 256>>>(G, b_reduce, Xt2h, Xt2l,
                                               f & 1, (f >> 1) * 256);
    }
    // conv2 via GEMM + shiftsum, 2 images
    for (int img = 0; img < 2; img++) {
        dim3 ggrid((NP + 127) / 128, MTOT / 128);
        gemm_mma_kernel<512><<<ggrid, 256, SMEM_GEMM>>>(
            A2h, A2l,
            Xt2h + (long long)img * NP * 512,
            Xt2l + (long long)img * NP * 512, G);
        dim3 sgrid((HWc + 255) / 256, 256);          // (66, 256)
        shiftsum_conv2_kernel<<<sgrid, 256>>>(G, b_conv2,
                                              x2 + (long long)img * 256 * HWc);
    }
    // conv3 (1x1, 256->49) + relu + softmax
    {
        int smem = 256 * 50 * sizeof(float);
        cudaFuncSetAttribute(conv3_softmax_kernel,
                             cudaFuncAttributeMaxDynamicSharedMemorySize, smem);
        int total = 2 * HWc;
        conv3_softmax_kernel<<<(total + 255) / 256, 256, smem>>>(
            x2, w_conv3, b_conv3, kern);
    }
    // spatially-variant 7x7 conv
    {
        dim3 grid(9, 9, 8);
        svconv_kernel<<<grid, 256>>>(key_high, kern, out);
    }
}

// round 15
// speedup vs baseline: 2.2084x; 1.1103x over previous
#include <cuda_runtime.h>
#include <cuda_bf16.h>
#include <math.h>
#include <stdint.h>

// ----------------------------------------------------------------------------
// AdaptiveFeaturePropagation — HMMA bf16 split GEMM, cp.async double-buffered
// ----------------------------------------------------------------------------

#define Hc   129
#define Wc   129
#define HWc  (129*129)
#define HIN  33
#define PW   131
#define NP   (131*131)
#define MTOT 2304

typedef unsigned long long u64;

__device__ __forceinline__ uint32_t smem_to_u32(const void* p) {
    uint32_t a;
    asm("{ .reg .u64 t; cvta.to.shared.u64 t, %1; cvt.u32.u64 %0, t; }"
        : "=r"(a) : "l"(p));
    return a;
}

#define LDSM_X4(r0, r1, r2, r3, addr) \
    asm volatile("ldmatrix.sync.aligned.m8n8.x4.shared.b16 {%0,%1,%2,%3}, [%4];" \
                 : "=r"(r0), "=r"(r1), "=r"(r2), "=r"(r3) : "r"(addr))

#define MMA_BF16(d, a, b) \
    asm volatile("mma.sync.aligned.m16n8k16.row.col.f32.bf16.bf16.f32 " \
                 "{%0,%1,%2,%3}, {%4,%5,%6,%7}, {%8,%9}, {%0,%1,%2,%3};" \
                 : "+f"((d)[0]), "+f"((d)[1]), "+f"((d)[2]), "+f"((d)[3]) \
                 : "r"((a)[0]), "r"((a)[1]), "r"((a)[2]), "r"((a)[3]), \
                   "r"((b)[0]), "r"((b)[1]))

__device__ __forceinline__ void cp16(uint32_t dst, const void* src) {
    asm volatile("cp.async.cg.shared.global [%0], [%1], 16;" :: "r"(dst), "l"(src));
}
__device__ __forceinline__ void cp16z(uint32_t dst, const void* src, int srcsize) {
    asm volatile("cp.async.cg.shared.global [%0], [%1], 16, %2;"
                 :: "r"(dst), "l"(src), "r"(srcsize));
}
#define CP_COMMIT() asm volatile("cp.async.commit_group;" ::: "memory")
#define CP_WAIT(n)  asm volatile("cp.async.wait_group %0;" :: "n"(n) : "memory")

// ------------------------------------------------------------- scratch ----
__device__ __nv_bfloat16 g_Xt1_hi[4ll * NP * 128];
__device__ __nv_bfloat16 g_Xt1_lo[4ll * NP * 128];
__device__ __nv_bfloat16 g_Xt2_hi[2ll * NP * 512];
__device__ __nv_bfloat16 g_Xt2_lo[2ll * NP * 512];
__device__ __nv_bfloat16 g_A1_hi[MTOT * 128];
__device__ __nv_bfloat16 g_A1_lo[MTOT * 128];
__device__ __nv_bfloat16 g_A2_hi[MTOT * 512];
__device__ __nv_bfloat16 g_A2_lo[MTOT * 512];
__device__ float g_G[(long long)MTOT * NP];
__device__ float g_x2[2ll * 256 * HWc];
__device__ float g_kern[2ll * 49 * HWc];

__device__ __forceinline__ void bf16_split(float v, __nv_bfloat16& hi, __nv_bfloat16& lo) {
    hi = __float2bfloat16(v);
    lo = __float2bfloat16(v - __bfloat162float(hi));
}

// ------------------------------------------- weight prep (hi/lo, re-order) --
__global__ void prep_w_kernel(const float* __restrict__ w, int CIN,
                              __nv_bfloat16* __restrict__ Ah,
                              __nv_bfloat16* __restrict__ Al)
{
    long long idx = (long long)blockIdx.x * blockDim.x + threadIdx.x;
    long long total = (long long)MTOT * CIN;
    if (idx >= total) return;
    int m  = (int)(idx / CIN);
    int ic = (int)(idx % CIN);
    int tap = m / 256, oc = m % 256;
    float v = w[((long long)oc * CIN + ic) * 9 + tap];
    __nv_bfloat16 h, l; bf16_split(v, h, l);
    Ah[idx] = h; Al[idx] = l;
}

// ---------------------------------------- upsample + split into NHWC pad ---
__global__ void upsample_split_kernel(const float* __restrict__ cur_low,
                                      const float* __restrict__ key_low,
                                      __nv_bfloat16* __restrict__ Xh,
                                      __nv_bfloat16* __restrict__ Xl)
{
    int pix = blockIdx.x;
    int f   = blockIdx.y;
    int ic  = threadIdx.x;
    int y = pix / Wc, x = pix % Wc;
    const float s = 33.0f / 129.0f;
    float sy = (y + 0.5f) * s - 0.5f;
    float sx = (x + 0.5f) * s - 0.5f;
    float fy = floorf(sy), fx = floorf(sx);
    int y0 = (int)fy, x0 = (int)fx;
    float wy = sy - fy, wx = sx - fx;
    int y0c = max(y0, 0), y1c = min(y0 + 1, HIN - 1);
    int x0c = max(x0, 0), x1c = min(x0 + 1, HIN - 1);
    const float* src = (f < 2) ? (cur_low + ((long long)f * 128 + ic) * (HIN * HIN))
                               : (key_low + ((long long)(f - 2) * 128 + ic) * (HIN * HIN));
    float v00 = src[y0c * HIN + x0c];
    float v01 = src[y0c * HIN + x1c];
    float v10 = src[y1c * HIN + x0c];
    float v11 = src[y1c * HIN + x1c];
    float v0 = v00 + (v01 - v00) * wx;
    float v1 = v10 + (v11 - v10) * wx;
    float v  = v0 + (v1 - v0) * wy;
    int ppad = (y + 1) * PW + (x + 1);
    long long o = ((long long)f * NP + ppad) * 128 + ic;
    __nv_bfloat16 h, l; bf16_split(v, h, l);
    Xh[o] = h; Xl[o] = l;
}

// ------------------------------------------------------- HMMA GEMM --------
// Double-buffered cp.async pipeline over K-slabs of 64.
static constexpr int SA_HI  = 0;
static constexpr int SA_LO  = 16384;
static constexpr int SBm_HI = 32768;
static constexpr int SBm_LO = 49152;
static constexpr int BUF_SZ = 65536;
static constexpr int SMEM_GEMM = 2 * BUF_SZ;   // 131072

template<int K>
__global__ __launch_bounds__(256)
void gemm_mma_kernel(const __nv_bfloat16* __restrict__ A_hi,
                     const __nv_bfloat16* __restrict__ A_lo,
                     const __nv_bfloat16* __restrict__ B_hi,
                     const __nv_bfloat16* __restrict__ B_lo,
                     float* __restrict__ G)
{
    extern __shared__ char smem[];
    const uint32_t sb = smem_to_u32(smem);
    const int tid  = threadIdx.x;
    const int wid  = tid >> 5;
    const int lane = tid & 31;
    const int wm = wid >> 2;
    const int wn = wid & 3;
    const int mt_blk = blockIdx.y;
    const int p0 = blockIdx.x * 128;
    const int NS = K / 64;

    float acc[4][4][4];
#pragma unroll
    for (int mi = 0; mi < 4; mi++)
#pragma unroll
        for (int ni = 0; ni < 4; ni++)
#pragma unroll
            for (int r = 0; r < 4; r++) acc[mi][ni][r] = 0.f;

    const int a_row_l = wm * 64 + (lane & 15);
    const int a_kb_l  = (lane >> 4) * 16;
    const int b_row_l = wn * 32 + (lane & 7) + ((lane >> 4) & 1) * 8;
    const int b_kb_l  = ((lane >> 3) & 1) * 16;

    // per-thread fill coords (4 x uint4 rows per tile)
    // i in {tid, tid+256, tid+512, tid+768}; r = i>>3, q = i&7
    auto fill_slab = [&](int s, uint32_t bufbase) {
        const int k0 = s * 64;
#pragma unroll
        for (int it = 0; it < 4; it++) {
            int i = it * 256 + tid;
            int r = i >> 3, q = i & 7;
            uint32_t off = (uint32_t)(r * 128 + ((q * 16) ^ ((r & 7) << 4)));
            long long ga = (long long)(mt_blk * 128 + r) * K + k0 + q * 8;
            cp16(sb + bufbase + SA_HI + off, A_hi + ga);
            cp16(sb + bufbase + SA_LO + off, A_lo + ga);
            int p = p0 + r;
            const __nv_bfloat16* gbh;
            const __nv_bfloat16* gbl;
            int sz;
            if (p < NP) {
                long long gb = (long long)p * K + k0 + q * 8;
                gbh = B_hi + gb; gbl = B_lo + gb; sz = 16;
            } else {
                gbh = B_hi; gbl = B_lo; sz = 0;
            }
            cp16z(sb + bufbase + SBm_HI + off, gbh, sz);
            cp16z(sb + bufbase + SBm_LO + off, gbl, sz);
        }
        CP_COMMIT();
    };

    fill_slab(0, 0);

    for (int s = 0; s < NS; s++) {
        const uint32_t bufc = (uint32_t)(s & 1) * BUF_SZ;
        const int nxt = s + 1;
        if (nxt < NS) {
            fill_slab(nxt, (uint32_t)(nxt & 1) * BUF_SZ);
            CP_WAIT(1);
        } else {
            CP_WAIT(0);
        }
        __syncthreads();

#pragma unroll
        for (int ks = 0; ks < 4; ks++) {
            const int kbase = ks * 32;
            uint32_t a_hi[4][4], a_lo[4][4], b_hi[4][2], b_lo[4][2];
#pragma unroll
            for (int mi = 0; mi < 4; mi++) {
                int row = a_row_l + mi * 16;
                uint32_t xm = (uint32_t)((row & 7) << 4);
                uint32_t adh = sb + bufc + SA_HI + row * 128 + ((kbase + a_kb_l) ^ xm);
                uint32_t adl = sb + bufc + SA_LO + row * 128 + ((kbase + a_kb_l) ^ xm);
                LDSM_X4(a_hi[mi][0], a_hi[mi][1], a_hi[mi][2], a_hi[mi][3], adh);
                LDSM_X4(a_lo[mi][0], a_lo[mi][1], a_lo[mi][2], a_lo[mi][3], adl);
            }
#pragma unroll
            for (int bt = 0; bt < 2; bt++) {
                int row = b_row_l + bt * 16;
                uint32_t xm = (uint32_t)((row & 7) << 4);
                uint32_t adh = sb + bufc + SBm_HI + row * 128 + ((kbase + b_kb_l) ^ xm);
                uint32_t adl = sb + bufc + SBm_LO + row * 128 + ((kbase + b_kb_l) ^ xm);
                LDSM_X4(b_hi[2 * bt][0], b_hi[2 * bt][1],
                        b_hi[2 * bt + 1][0], b_hi[2 * bt + 1][1], adh);
                LDSM_X4(b_lo[2 * bt][0], b_lo[2 * bt][1],
                        b_lo[2 * bt + 1][0], b_lo[2 * bt + 1][1], adl);
            }
#pragma unroll
            for (int mi = 0; mi < 4; mi++)
#pragma unroll
                for (int ni = 0; ni < 4; ni++) {
                    MMA_BF16(acc[mi][ni], a_hi[mi], b_hi[ni]);
                    MMA_BF16(acc[mi][ni], a_hi[mi], b_lo[ni]);
                    MMA_BF16(acc[mi][ni], a_lo[mi], b_hi[ni]);
                }
        }
        __syncthreads();
    }

    // ---- epilogue: accum fragments -> G[m][p] ----
    const int m_base = mt_blk * 128 + wm * 64 + (lane >> 2);
    const int p_base = p0 + wn * 32 + (lane & 3) * 2;
#pragma unroll
    for (int mi = 0; mi < 4; mi++) {
#pragma unroll
        for (int ni = 0; ni < 4; ni++) {
            int m = m_base + mi * 16;
            int p = p_base + ni * 8;
            float* g0 = G + (long long)m * NP;
            float* g1 = g0 + 8ll * NP;
            if (p < NP)     { g0[p] = acc[mi][ni][0]; g1[p] = acc[mi][ni][2]; }
            if (p + 1 < NP) { g0[p + 1] = acc[mi][ni][1]; g1[p + 1] = acc[mi][ni][3]; }
        }
    }
}

// --------------------------------- shifted tap-sum epilogues ---------------
__global__ __launch_bounds__(256)
void shiftsum_reduce_kernel(const float* __restrict__ G,
                            const float* __restrict__ bias,
                            __nv_bfloat16* __restrict__ Xh,
                            __nv_bfloat16* __restrict__ Xl,
                            int img, int cbase)
{
    __shared__ float t[64][65];
    const int tid = threadIdx.x;
    const int x0  = blockIdx.x * 64;
    const int y   = blockIdx.y;
    const int oc0 = blockIdx.z * 64;

#pragma unroll 1
    for (int it = 0; it < 16; it++) {
        int idx = it * 256 + tid;
        int ocl = idx >> 6, px = idx & 63;
        int xx = x0 + px;
        float v = 0.f;
        if (xx < Wc) {
            int oc = oc0 + ocl;
            v = bias[oc];
#pragma unroll
            for (int kh = 0; kh < 3; kh++)
#pragma unroll
                for (int kw = 0; kw < 3; kw++) {
                    int tap = kh * 3 + kw;
                    v += G[(long long)(tap * 256 + oc) * NP + (y + kh) * PW + xx + kw];
                }
            v = fmaxf(v, 0.f);
        }
        t[ocl][px] = v;
    }
    __syncthreads();
#pragma unroll 1
    for (int it = 0; it < 16; it++) {
        int idx = it * 256 + tid;
        int px = idx >> 6, ocl = idx & 63;
        int xx = x0 + px;
        if (xx < Wc) {
            int ppad = (y + 1) * PW + xx + 1;
            long long o = ((long long)img * NP + ppad) * 512 + cbase + oc0 + ocl;
            float v = t[ocl][px];
            __nv_bfloat16 h, l; bf16_split(v, h, l);
            Xh[o] = h; Xl[o] = l;
        }
    }
}

__global__ __launch_bounds__(256)
void shiftsum_conv2_kernel(const float* __restrict__ G,
                           const float* __restrict__ bias,
                           float* __restrict__ x2img)
{
    int oc  = blockIdx.y;
    int pix = blockIdx.x * 256 + threadIdx.x;
    if (pix >= HWc) return;
    int y = pix / Wc, x = pix % Wc;
    float v = bias[oc];
#pragma unroll
    for (int kh = 0; kh < 3; kh++)
#pragma unroll
        for (int kw = 0; kw < 3; kw++) {
            int tap = kh * 3 + kw;
            v += G[(long long)(tap * 256 + oc) * NP + (y + kh) * PW + x + kw];
        }
    x2img[(long long)oc * HWc + pix] = fmaxf(v, 0.f);
}

// --------------------------------------------- 1x1 conv + relu + softmax   --
__device__ __forceinline__ u64 fma2(u64 a, u64 b, u64 c) {
    u64 d;
    asm("fma.rn.f32x2 %0, %1, %2, %3;" : "=l"(d) : "l"(a), "l"(b), "l"(c));
    return d;
}
__device__ __forceinline__ u64 pack2(float lo, float hi) {
    u64 d;
    asm("mov.b64 %0, {%1, %2};" : "=l"(d) : "f"(lo), "f"(hi));
    return d;
}
__device__ __forceinline__ float2 unpack2(u64 v) {
    float2 r;
    asm("mov.b64 {%0, %1}, %2;" : "=f"(r.x), "=f"(r.y) : "l"(v));
    return r;
}

__global__ __launch_bounds__(256)
void conv3_softmax_kernel(const float* __restrict__ x,
                          const float* __restrict__ w3,
                          const float* __restrict__ b3,
                          float* __restrict__ kout)
{
    extern __shared__ float ws[];
    for (int idx = threadIdx.x; idx < 256 * 50; idx += 256) {
        int c = idx / 50, oc = idx % 50;
        ws[idx] = (oc < 49) ? w3[oc * 256 + c] : 0.f;
    }
    __syncthreads();

    int p = blockIdx.x * 256 + threadIdx.x;
    if (p >= 2 * HWc) return;
    int n = p / HWc, pix = p % HWc;
    const float* xb = x + (long long)n * 256 * HWc + pix;

    u64 acc2[24];
#pragma unroll
    for (int q = 0; q < 24; q++) acc2[q] = 0ull;
    float acc48 = 0.f;

#pragma unroll 4
    for (int c = 0; c < 256; c++) {
        float xv = xb[(long long)c * HWc];
        u64 xd = pack2(xv, xv);
        const u64* wr = (const u64*)&ws[c * 50];
#pragma unroll
        for (int q = 0; q < 24; q++) acc2[q] = fma2(wr[q], xd, acc2[q]);
        acc48 += xv * ws[c * 50 + 48];
    }

    float a[49];
#pragma unroll
    for (int q = 0; q < 24; q++) {
        float2 v = unpack2(acc2[q]);
        a[2 * q] = v.x; a[2 * q + 1] = v.y;
    }
    a[48] = acc48;

    float m = -1e30f;
#pragma unroll
    for (int oc = 0; oc < 49; oc++) {
        a[oc] = fmaxf(a[oc] + b3[oc], 0.f);
        m = fmaxf(m, a[oc]);
    }
    float ssum = 0.f;
#pragma unroll
    for (int oc = 0; oc < 49; oc++) {
        a[oc] = __expf(a[oc] - m);
        ssum += a[oc];
    }
    float inv = 1.f / ssum;
    float* kb = kout + (long long)n * 49 * HWc + pix;
#pragma unroll
    for (int oc = 0; oc < 49; oc++) kb[(long long)oc * HWc] = a[oc] * inv;
}

// --------------------------------------------- spatially-variant 7x7 conv  --
__global__ __launch_bounds__(256)
void svconv_kernel(const float* __restrict__ feat,
                   const float* __restrict__ kern,
                   float* __restrict__ out)
{
    constexpr int TS = 16, PAD = 3, FT = TS + 2 * PAD;
    __shared__ float sf[2][FT * FT];

    const int tid = threadIdx.x;
    const int txi = tid & 15, tyi = tid >> 4;
    const int bx = blockIdx.x * TS, by = blockIdx.y * TS;
    const int n = blockIdx.z >> 2;
    const int c0 = (blockIdx.z & 3) * 64;
    const int x = bx + txi, y = by + tyi;
    const bool valid = (x < Wc) && (y < Hc);

    float kv[49];
    if (valid) {
        const float* kb = kern + (long long)n * 49 * HWc + y * Wc + x;
#pragma unroll
        for (int t = 0; t < 49; t++) kv[t] = kb[(long long)t * HWc];
    } else {
#pragma unroll
        for (int t = 0; t < 49; t++) kv[t] = 0.f;
    }

    const float* fb = feat + ((long long)n * 256 + c0) * HWc;
    float* ob = out + ((long long)n * 256 + c0) * HWc;

    for (int cl = 0; cl < 64; cl++) {
        const int buf = cl & 1;
        const float* fc = fb + (long long)cl * HWc;
        for (int idx = tid; idx < FT * FT; idx += 256) {
            int r = idx / FT, cc = idx % FT;
            int gy = by - PAD + r, gx = bx - PAD + cc;
            float v = 0.f;
            if ((unsigned)gy < Hc && (unsigned)gx < Wc) v = fc[gy * Wc + gx];
            sf[buf][idx] = v;
        }
        __syncthreads();
        if (valid) {
            float a = 0.f;
#pragma unroll
            for (int i = 0; i < 7; i++)
#pragma unroll
                for (int j = 0; j < 7; j++)
                    a += kv[i * 7 + j] * sf[buf][(tyi + i) * FT + txi + j];
            ob[(long long)cl * HWc + y * Wc + x] = a;
        }
    }
}

// ---------------------------------------------------------------------------
extern "C" void kernel_launch(void* const* d_in, const int* in_sizes, int n_in,
                              void* d_out, int out_size)
{
    const float* cur_low  = (const float*)d_in[0];
    const float* key_low  = (const float*)d_in[1];
    const float* key_high = (const float*)d_in[2];
    const float* w_reduce = (const float*)d_in[3];
    const float* b_reduce = (const float*)d_in[4];
    const float* w_conv2  = (const float*)d_in[5];
    const float* b_conv2  = (const float*)d_in[6];
    const float* w_conv3  = (const float*)d_in[7];
    const float* b_conv3  = (const float*)d_in[8];
    float* out = (float*)d_out;

    __nv_bfloat16 *Xt1h, *Xt1l, *Xt2h, *Xt2l, *A1h, *A1l, *A2h, *A2l;
    float *G, *x2, *kern;
    cudaGetSymbolAddress((void**)&Xt1h, g_Xt1_hi);
    cudaGetSymbolAddress((void**)&Xt1l, g_Xt1_lo);
    cudaGetSymbolAddress((void**)&Xt2h, g_Xt2_hi);
    cudaGetSymbolAddress((void**)&Xt2l, g_Xt2_lo);
    cudaGetSymbolAddress((void**)&A1h, g_A1_hi);
    cudaGetSymbolAddress((void**)&A1l, g_A1_lo);
    cudaGetSymbolAddress((void**)&A2h, g_A2_hi);
    cudaGetSymbolAddress((void**)&A2l, g_A2_lo);
    cudaGetSymbolAddress((void**)&G, g_G);
    cudaGetSymbolAddress((void**)&x2, g_x2);
    cudaGetSymbolAddress((void**)&kern, g_kern);

    cudaFuncSetAttribute(gemm_mma_kernel<128>,
                         cudaFuncAttributeMaxDynamicSharedMemorySize, SMEM_GEMM);
    cudaFuncSetAttribute(gemm_mma_kernel<512>,
                         cudaFuncAttributeMaxDynamicSharedMemorySize, SMEM_GEMM);

    // weight prep
    {
        long long t1 = (long long)MTOT * 128;
        prep_w_kernel<<<(unsigned)((t1 + 255) / 256), 256>>>(w_reduce, 128, A1h, A1l);
        long long t2 = (long long)MTOT * 512;
        prep_w_kernel<<<(unsigned)((t2 + 255) / 256), 256>>>(w_conv2, 512, A2h, A2l);
    }
    // upsample + split into NHWC padded
    {
        dim3 grid(HWc, 4);
        upsample_split_kernel<<<grid, 128>>>(cur_low, key_low, Xt1h, Xt1l);
    }
    // conv_reduce via GEMM + shiftsum, 4 frames
    for (int f = 0; f < 4; f++) {
        dim3 ggrid((NP + 127) / 128, MTOT / 128);
        gemm_mma_kernel<128><<<ggrid, 256, SMEM_GEMM>>>(
            A1h, A1l,
            Xt1h + (long long)f * NP * 128,
            Xt1l + (long long)f * NP * 128, G);
        dim3 sgrid((Wc + 63) / 64, Hc, 4);
        shiftsum_reduce_kernel<<<sgrid, 256>>>(G, b_reduce, Xt2h, Xt2l,
                                               f & 1, (f >> 1) * 256);
    }
    // conv2 via GEMM + shiftsum, 2 images
    for (int img = 0; img < 2; img++) {
        dim3 ggrid((NP + 127) / 128, MTOT / 128);
        gemm_mma_kernel<512><<<ggrid, 256, SMEM_GEMM>>>(
            A2h, A2l,
            Xt2h + (long long)img * NP * 512,
            Xt2l + (long long)img * NP * 512, G);
        dim3 sgrid((HWc + 255) / 256, 256);
        shiftsum_conv2_kernel<<<sgrid, 256>>>(G, b_conv2,
                                              x2 + (long long)img * 256 * HWc);
    }
    // conv3 (1x1, 256->49) + relu + softmax
    {
        int smem = 256 * 50 * sizeof(float);
        cudaFuncSetAttribute(conv3_softmax_kernel,
                             cudaFuncAttributeMaxDynamicSharedMemorySize, smem);
        int total = 2 * HWc;
        conv3_softmax_kernel<<<(total + 255) / 256, 256, smem>>>(
            x2, w_conv3, b_conv3, kern);
    }
    // spatially-variant 7x7 conv
    {
        dim3 grid(9, 9, 8);
        svconv_kernel<<<grid, 256>>>(key_high, kern, out);
    }
}

// round 16
// speedup vs baseline: 3.1100x; 1.4083x over previous
#include <cuda_runtime.h>
#include <cuda_bf16.h>
#include <math.h>
#include <stdint.h>

// ----------------------------------------------------------------------------
// AdaptiveFeaturePropagation — HMMA bf16 split GEMM, taps folded into K
//   out[oc, p] = sum_{tap,ic} W[oc, tap*CIN+ic] * Xpad[p + off(tap), ic]
//   (single GEMM per conv layer, epilogue fused, no G intermediate)
// ----------------------------------------------------------------------------

#define Hc   129
#define Wc   129
#define HWc  (129*129)
#define HIN  33
#define PW   131
#define NP   (131*131)

typedef unsigned long long u64;

__device__ __forceinline__ uint32_t smem_to_u32(const void* p) {
    uint32_t a;
    asm("{ .reg .u64 t; cvta.to.shared.u64 t, %1; cvt.u32.u64 %0, t; }"
        : "=r"(a) : "l"(p));
    return a;
}

#define LDSM_X4(r0, r1, r2, r3, addr) \
    asm volatile("ldmatrix.sync.aligned.m8n8.x4.shared.b16 {%0,%1,%2,%3}, [%4];" \
                 : "=r"(r0), "=r"(r1), "=r"(r2), "=r"(r3) : "r"(addr))

#define MMA_BF16(d, a, b) \
    asm volatile("mma.sync.aligned.m16n8k16.row.col.f32.bf16.bf16.f32 " \
                 "{%0,%1,%2,%3}, {%4,%5,%6,%7}, {%8,%9}, {%0,%1,%2,%3};" \
                 : "+f"((d)[0]), "+f"((d)[1]), "+f"((d)[2]), "+f"((d)[3]) \
                 : "r"((a)[0]), "r"((a)[1]), "r"((a)[2]), "r"((a)[3]), \
                   "r"((b)[0]), "r"((b)[1]))

__device__ __forceinline__ void cp16(uint32_t dst, const void* src) {
    asm volatile("cp.async.cg.shared.global [%0], [%1], 16;" :: "r"(dst), "l"(src));
}
__device__ __forceinline__ void cp16z(uint32_t dst, const void* src, int srcsize) {
    asm volatile("cp.async.cg.shared.global [%0], [%1], 16, %2;"
                 :: "r"(dst), "l"(src), "r"(srcsize));
}
#define CP_COMMIT() asm volatile("cp.async.commit_group;" ::: "memory")
#define CP_WAIT(n)  asm volatile("cp.async.wait_group %0;" :: "n"(n) : "memory")

// ------------------------------------------------------------- scratch ----
__device__ __nv_bfloat16 g_Xt1_hi[4ll * NP * 128];   // upsampled feats, NHWC padded
__device__ __nv_bfloat16 g_Xt1_lo[4ll * NP * 128];
__device__ __nv_bfloat16 g_Xt2_hi[2ll * NP * 512];   // concat reduce outputs
__device__ __nv_bfloat16 g_Xt2_lo[2ll * NP * 512];
__device__ __nv_bfloat16 g_A1_hi[256 * 9 * 128];     // w_reduce [oc][tap*128+ic]
__device__ __nv_bfloat16 g_A1_lo[256 * 9 * 128];
__device__ __nv_bfloat16 g_A2_hi[256 * 9 * 512];     // w_conv2  [oc][tap*512+ic]
__device__ __nv_bfloat16 g_A2_lo[256 * 9 * 512];
__device__ float g_x2[2ll * 256 * HWc];
__device__ float g_kern[2ll * 49 * HWc];

__device__ __forceinline__ void bf16_split(float v, __nv_bfloat16& hi, __nv_bfloat16& lo) {
    hi = __float2bfloat16(v);
    lo = __float2bfloat16(v - __bfloat162float(hi));
}

// ------------------------------------------- weight prep (hi/lo, re-order) --
// out layout: [oc][tap*CIN + ic]
__global__ void prep_w_kernel(const float* __restrict__ w, int CIN,
                              __nv_bfloat16* __restrict__ Ah,
                              __nv_bfloat16* __restrict__ Al)
{
    long long idx = (long long)blockIdx.x * blockDim.x + threadIdx.x;
    long long total = 256ll * 9 * CIN;
    if (idx >= total) return;
    int Ktot = 9 * CIN;
    int oc = (int)(idx / Ktot);
    int k  = (int)(idx % Ktot);
    int tap = k / CIN, ic = k % CIN;
    float v = w[((long long)oc * CIN + ic) * 9 + tap];
    __nv_bfloat16 h, l; bf16_split(v, h, l);
    Ah[idx] = h; Al[idx] = l;
}

// ---------------------------------------- upsample + split into NHWC pad ---
__global__ void upsample_split_kernel(const float* __restrict__ cur_low,
                                      const float* __restrict__ key_low,
                                      __nv_bfloat16* __restrict__ Xh,
                                      __nv_bfloat16* __restrict__ Xl)
{
    int pix = blockIdx.x;
    int f   = blockIdx.y;
    int ic  = threadIdx.x;
    int y = pix / Wc, x = pix % Wc;
    const float s = 33.0f / 129.0f;
    float sy = (y + 0.5f) * s - 0.5f;
    float sx = (x + 0.5f) * s - 0.5f;
    float fy = floorf(sy), fx = floorf(sx);
    int y0 = (int)fy, x0 = (int)fx;
    float wy = sy - fy, wx = sx - fx;
    int y0c = max(y0, 0), y1c = min(y0 + 1, HIN - 1);
    int x0c = max(x0, 0), x1c = min(x0 + 1, HIN - 1);
    const float* src = (f < 2) ? (cur_low + ((long long)f * 128 + ic) * (HIN * HIN))
                               : (key_low + ((long long)(f - 2) * 128 + ic) * (HIN * HIN));
    float v00 = src[y0c * HIN + x0c];
    float v01 = src[y0c * HIN + x1c];
    float v10 = src[y1c * HIN + x0c];
    float v11 = src[y1c * HIN + x1c];
    float v0 = v00 + (v01 - v00) * wx;
    float v1 = v10 + (v11 - v10) * wx;
    float v  = v0 + (v1 - v0) * wy;
    int ppad = (y + 1) * PW + (x + 1);
    long long o = ((long long)f * NP + ppad) * 128 + ic;
    __nv_bfloat16 h, l; bf16_split(v, h, l);
    Xh[o] = h; Xl[o] = l;
}

// ------------------------------------------------------- HMMA GEMM --------
// Taps folded into K: Ktot = 9*CIN. Per 64-slab: tap = k0/CIN, B rows shifted
// by off(tap), OOB rows zero-filled. Double-buffered cp.async.
// Epilogue fused: REDUCE -> bias+relu+bf16split into Xt2; else fp32 into x2.
static constexpr int SA_HI  = 0;
static constexpr int SA_LO  = 16384;
static constexpr int SBm_HI = 32768;
static constexpr int SBm_LO = 49152;
static constexpr int BUF_SZ = 65536;
static constexpr int SMEM_GEMM = 2 * BUF_SZ;   // 131072

template<int CIN, bool REDUCE>
__global__ __launch_bounds__(256)
void gemm_conv_kernel(const __nv_bfloat16* __restrict__ A_hi,
                      const __nv_bfloat16* __restrict__ A_lo,
                      const __nv_bfloat16* __restrict__ Xbase_hi,
                      const __nv_bfloat16* __restrict__ Xbase_lo,
                      const float* __restrict__ bias,
                      __nv_bfloat16* __restrict__ OXh,   // REDUCE out (hi)
                      __nv_bfloat16* __restrict__ OXl,   // REDUCE out (lo)
                      float* __restrict__ Ofp)           // conv2 out
{
    constexpr int KTOT = 9 * CIN;
    constexpr int NS   = KTOT / 64;
    extern __shared__ char smem[];
    const uint32_t sb = smem_to_u32(smem);
    const int tid  = threadIdx.x;
    const int wid  = tid >> 5;
    const int lane = tid & 31;
    const int wm = wid >> 2;
    const int wn = wid & 3;
    const int mt = blockIdx.y;               // 0..1 (oc tile of 128)
    const int p0 = blockIdx.x * 128;
    const int f  = blockIdx.z;               // frame / image

    const __nv_bfloat16* B_hi = Xbase_hi + (long long)f * NP * CIN;
    const __nv_bfloat16* B_lo = Xbase_lo + (long long)f * NP * CIN;

    float acc[4][4][4];
#pragma unroll
    for (int mi = 0; mi < 4; mi++)
#pragma unroll
        for (int ni = 0; ni < 4; ni++)
#pragma unroll
            for (int r = 0; r < 4; r++) acc[mi][ni][r] = 0.f;

    const int a_row_l = wm * 64 + (lane & 15);
    const int a_kb_l  = (lane >> 4) * 16;
    const int b_row_l = wn * 32 + (lane & 7) + ((lane >> 4) & 1) * 8;
    const int b_kb_l  = ((lane >> 3) & 1) * 16;

    auto fill_slab = [&](int s, uint32_t bufbase) {
        const int k0   = s * 64;
        const int tap  = k0 / CIN;
        const int koff = k0 % CIN;
        const int off  = (tap / 3 - 1) * PW + (tap % 3 - 1);
#pragma unroll
        for (int it = 0; it < 4; it++) {
            int i = it * 256 + tid;
            int r = i >> 3, q = i & 7;
            uint32_t soff = (uint32_t)(r * 128 + ((q * 16) ^ ((r & 7) << 4)));
            long long ga = (long long)(mt * 128 + r) * KTOT + k0 + q * 8;
            cp16(sb + bufbase + SA_HI + soff, A_hi + ga);
            cp16(sb + bufbase + SA_LO + soff, A_lo + ga);
            int rp = p0 + r + off;
            const __nv_bfloat16* gbh = B_hi;
            const __nv_bfloat16* gbl = B_lo;
            int sz = 0;
            if ((unsigned)rp < (unsigned)NP) {
                long long gb = (long long)rp * CIN + koff + q * 8;
                gbh = B_hi + gb; gbl = B_lo + gb; sz = 16;
            }
            cp16z(sb + bufbase + SBm_HI + soff, gbh, sz);
            cp16z(sb + bufbase + SBm_LO + soff, gbl, sz);
        }
        CP_COMMIT();
    };

    fill_slab(0, 0);

    for (int s = 0; s < NS; s++) {
        const uint32_t bufc = (uint32_t)(s & 1) * BUF_SZ;
        if (s + 1 < NS) {
            fill_slab(s + 1, (uint32_t)((s + 1) & 1) * BUF_SZ);
            CP_WAIT(1);
        } else {
            CP_WAIT(0);
        }
        __syncthreads();

#pragma unroll
        for (int ks = 0; ks < 4; ks++) {
            const int kbase = ks * 32;
            uint32_t a_hi[4][4], a_lo[4][4], b_hi[4][2], b_lo[4][2];
#pragma unroll
            for (int mi = 0; mi < 4; mi++) {
                int row = a_row_l + mi * 16;
                uint32_t xm = (uint32_t)((row & 7) << 4);
                uint32_t adh = sb + bufc + SA_HI + row * 128 + ((kbase + a_kb_l) ^ xm);
                uint32_t adl = sb + bufc + SA_LO + row * 128 + ((kbase + a_kb_l) ^ xm);
                LDSM_X4(a_hi[mi][0], a_hi[mi][1], a_hi[mi][2], a_hi[mi][3], adh);
                LDSM_X4(a_lo[mi][0], a_lo[mi][1], a_lo[mi][2], a_lo[mi][3], adl);
            }
#pragma unroll
            for (int bt = 0; bt < 2; bt++) {
                int row = b_row_l + bt * 16;
                uint32_t xm = (uint32_t)((row & 7) << 4);
                uint32_t adh = sb + bufc + SBm_HI + row * 128 + ((kbase + b_kb_l) ^ xm);
                uint32_t adl = sb + bufc + SBm_LO + row * 128 + ((kbase + b_kb_l) ^ xm);
                LDSM_X4(b_hi[2 * bt][0], b_hi[2 * bt][1],
                        b_hi[2 * bt + 1][0], b_hi[2 * bt + 1][1], adh);
                LDSM_X4(b_lo[2 * bt][0], b_lo[2 * bt][1],
                        b_lo[2 * bt + 1][0], b_lo[2 * bt + 1][1], adl);
            }
#pragma unroll
            for (int mi = 0; mi < 4; mi++)
#pragma unroll
                for (int ni = 0; ni < 4; ni++) {
                    MMA_BF16(acc[mi][ni], a_hi[mi], b_hi[ni]);
                    MMA_BF16(acc[mi][ni], a_hi[mi], b_lo[ni]);
                    MMA_BF16(acc[mi][ni], a_lo[mi], b_hi[ni]);
                }
        }
        __syncthreads();
    }

    // ---- fused epilogue ----
    const int oc_base = mt * 128 + wm * 64 + (lane >> 2);
    const int p_base  = p0 + wn * 32 + (lane & 3) * 2;

    // precompute interior mapping for the 8 pixel columns this thread owns
    int pix_out[4][2]; // [ni][r&1]
#pragma unroll
    for (int ni = 0; ni < 4; ni++)
#pragma unroll
        for (int d = 0; d < 2; d++) {
            int p = p_base + ni * 8 + d;
            int yp = p / PW, xp = p % PW;
            bool inter = (p < NP) && (yp >= 1) && (yp <= Hc) && (xp >= 1) && (xp <= Wc);
            pix_out[ni][d] = inter ? ((yp - 1) * Wc + (xp - 1)) : -1;
        }

    float bs[4][2];
#pragma unroll
    for (int mi = 0; mi < 4; mi++) {
        bs[mi][0] = bias[oc_base + mi * 16];
        bs[mi][1] = bias[oc_base + mi * 16 + 8];
    }

#pragma unroll
    for (int mi = 0; mi < 4; mi++) {
#pragma unroll
        for (int ni = 0; ni < 4; ni++) {
#pragma unroll
            for (int r = 0; r < 4; r++) {
                int oc = oc_base + mi * 16 + (r >> 1) * 8;
                int d  = r & 1;
                int pix = pix_out[ni][d];
                if (pix < 0) continue;
                float v = fmaxf(acc[mi][ni][r] + bs[mi][r >> 1], 0.f);
                if (REDUCE) {
                    // Xt2 channel = cbase + oc ; cbase = (f>>1)*256, img = f&1
                    int p = p_base + ni * 8 + d;
                    long long o = ((long long)(f & 1) * NP + p) * 512
                                + (f >> 1) * 256 + oc;
                    __nv_bfloat16 h, l; bf16_split(v, h, l);
                    OXh[o] = h; OXl[o] = l;
                } else {
                    Ofp[((long long)f * 256 + oc) * HWc + pix] = v;
                }
            }
        }
    }
}

// --------------------------------------------- 1x1 conv + relu + softmax   --
__device__ __forceinline__ u64 fma2(u64 a, u64 b, u64 c) {
    u64 d;
    asm("fma.rn.f32x2 %0, %1, %2, %3;" : "=l"(d) : "l"(a), "l"(b), "l"(c));
    return d;
}
__device__ __forceinline__ u64 pack2(float lo, float hi) {
    u64 d;
    asm("mov.b64 %0, {%1, %2};" : "=l"(d) : "f"(lo), "f"(hi));
    return d;
}
__device__ __forceinline__ float2 unpack2(u64 v) {
    float2 r;
    asm("mov.b64 {%0, %1}, %2;" : "=f"(r.x), "=f"(r.y) : "l"(v));
    return r;
}

__global__ __launch_bounds__(256)
void conv3_softmax_kernel(const float* __restrict__ x,
                          const float* __restrict__ w3,
                          const float* __restrict__ b3,
                          float* __restrict__ kout)
{
    extern __shared__ float ws[];
    for (int idx = threadIdx.x; idx < 256 * 50; idx += 256) {
        int c = idx / 50, oc = idx % 50;
        ws[idx] = (oc < 49) ? w3[oc * 256 + c] : 0.f;
    }
    __syncthreads();

    int p = blockIdx.x * 256 + threadIdx.x;
    if (p >= 2 * HWc) return;
    int n = p / HWc, pix = p % HWc;
    const float* xb = x + (long long)n * 256 * HWc + pix;

    u64 acc2[24];
#pragma unroll
    for (int q = 0; q < 24; q++) acc2[q] = 0ull;
    float acc48 = 0.f;

#pragma unroll 4
    for (int c = 0; c < 256; c++) {
        float xv = xb[(long long)c * HWc];
        u64 xd = pack2(xv, xv);
        const u64* wr = (const u64*)&ws[c * 50];
#pragma unroll
        for (int q = 0; q < 24; q++) acc2[q] = fma2(wr[q], xd, acc2[q]);
        acc48 += xv * ws[c * 50 + 48];
    }

    float a[49];
#pragma unroll
    for (int q = 0; q < 24; q++) {
        float2 v = unpack2(acc2[q]);
        a[2 * q] = v.x; a[2 * q + 1] = v.y;
    }
    a[48] = acc48;

    float m = -1e30f;
#pragma unroll
    for (int oc = 0; oc < 49; oc++) {
        a[oc] = fmaxf(a[oc] + b3[oc], 0.f);
        m = fmaxf(m, a[oc]);
    }
    float ssum = 0.f;
#pragma unroll
    for (int oc = 0; oc < 49; oc++) {
        a[oc] = __expf(a[oc] - m);
        ssum += a[oc];
    }
    float inv = 1.f / ssum;
    float* kb = kout + (long long)n * 49 * HWc + pix;
#pragma unroll
    for (int oc = 0; oc < 49; oc++) kb[(long long)oc * HWc] = a[oc] * inv;
}

// --------------------------------------------- spatially-variant 7x7 conv  --
__global__ __launch_bounds__(256)
void svconv_kernel(const float* __restrict__ feat,
                   const float* __restrict__ kern,
                   float* __restrict__ out)
{
    constexpr int TS = 16, PAD = 3, FT = TS + 2 * PAD;
    __shared__ float sf[2][FT * FT];

    const int tid = threadIdx.x;
    const int txi = tid & 15, tyi = tid >> 4;
    const int bx = blockIdx.x * TS, by = blockIdx.y * TS;
    const int n = blockIdx.z >> 2;
    const int c0 = (blockIdx.z & 3) * 64;
    const int x = bx + txi, y = by + tyi;
    const bool valid = (x < Wc) && (y < Hc);

    float kv[49];
    if (valid) {
        const float* kb = kern + (long long)n * 49 * HWc + y * Wc + x;
#pragma unroll
        for (int t = 0; t < 49; t++) kv[t] = kb[(long long)t * HWc];
    } else {
#pragma unroll
        for (int t = 0; t < 49; t++) kv[t] = 0.f;
    }

    const float* fb = feat + ((long long)n * 256 + c0) * HWc;
    float* ob = out + ((long long)n * 256 + c0) * HWc;

    for (int cl = 0; cl < 64; cl++) {
        const int buf = cl & 1;
        const float* fc = fb + (long long)cl * HWc;
        for (int idx = tid; idx < FT * FT; idx += 256) {
            int r = idx / FT, cc = idx % FT;
            int gy = by - PAD + r, gx = bx - PAD + cc;
            float v = 0.f;
            if ((unsigned)gy < Hc && (unsigned)gx < Wc) v = fc[gy * Wc + gx];
            sf[buf][idx] = v;
        }
        __syncthreads();
        if (valid) {
            float a = 0.f;
#pragma unroll
            for (int i = 0; i < 7; i++)
#pragma unroll
                for (int j = 0; j < 7; j++)
                    a += kv[i * 7 + j] * sf[buf][(tyi + i) * FT + txi + j];
            ob[(long long)cl * HWc + y * Wc + x] = a;
        }
    }
}

// ---------------------------------------------------------------------------
extern "C" void kernel_launch(void* const* d_in, const int* in_sizes, int n_in,
                              void* d_out, int out_size)
{
    const float* cur_low  = (const float*)d_in[0];
    const float* key_low  = (const float*)d_in[1];
    const float* key_high = (const float*)d_in[2];
    const float* w_reduce = (const float*)d_in[3];
    const float* b_reduce = (const float*)d_in[4];
    const float* w_conv2  = (const float*)d_in[5];
    const float* b_conv2  = (const float*)d_in[6];
    const float* w_conv3  = (const float*)d_in[7];
    const float* b_conv3  = (const float*)d_in[8];
    float* out = (float*)d_out;

    __nv_bfloat16 *Xt1h, *Xt1l, *Xt2h, *Xt2l, *A1h, *A1l, *A2h, *A2l;
    float *x2, *kern;
    cudaGetSymbolAddress((void**)&Xt1h, g_Xt1_hi);
    cudaGetSymbolAddress((void**)&Xt1l, g_Xt1_lo);
    cudaGetSymbolAddress((void**)&Xt2h, g_Xt2_hi);
    cudaGetSymbolAddress((void**)&Xt2l, g_Xt2_lo);
    cudaGetSymbolAddress((void**)&A1h, g_A1_hi);
    cudaGetSymbolAddress((void**)&A1l, g_A1_lo);
    cudaGetSymbolAddress((void**)&A2h, g_A2_hi);
    cudaGetSymbolAddress((void**)&A2l, g_A2_lo);
    cudaGetSymbolAddress((void**)&x2, g_x2);
    cudaGetSymbolAddress((void**)&kern, g_kern);

    cudaFuncSetAttribute((const void*)gemm_conv_kernel<128, true>,
                         cudaFuncAttributeMaxDynamicSharedMemorySize, SMEM_GEMM);
    cudaFuncSetAttribute((const void*)gemm_conv_kernel<512, false>,
                         cudaFuncAttributeMaxDynamicSharedMemorySize, SMEM_GEMM);

    // weight prep: [oc][tap*CIN+ic] hi/lo
    {
        long long t1 = 256ll * 9 * 128;
        prep_w_kernel<<<(unsigned)((t1 + 255) / 256), 256>>>(w_reduce, 128, A1h, A1l);
        long long t2 = 256ll * 9 * 512;
        prep_w_kernel<<<(unsigned)((t2 + 255) / 256), 256>>>(w_conv2, 512, A2h, A2l);
    }
    // upsample + split into NHWC padded (4 frames)
    {
        dim3 grid(HWc, 4);
        upsample_split_kernel<<<grid, 128>>>(cur_low, key_low, Xt1h, Xt1l);
    }
    // conv_reduce: single batched GEMM, epilogue writes concat Xt2 (hi/lo)
    {
        dim3 ggrid((NP + 127) / 128, 2, 4);   // (135, 2, 4)
        gemm_conv_kernel<128, true><<<ggrid, 256, SMEM_GEMM>>>(
            A1h, A1l, Xt1h, Xt1l, b_reduce, Xt2h, Xt2l, nullptr);
    }
    // conv2: single batched GEMM, epilogue writes fp32 x2
    {
        dim3 ggrid((NP + 127) / 128, 2, 2);   // (135, 2, 2)
        gemm_conv_kernel<512, false><<<ggrid, 256, SMEM_GEMM>>>(
            A2h, A2l, Xt2h, Xt2l, b_conv2, nullptr, nullptr, x2);
    }
    // conv3 (1x1, 256->49) + relu + softmax
    {
        int smem = 256 * 50 * sizeof(float);
        cudaFuncSetAttribute(conv3_softmax_kernel,
                             cudaFuncAttributeMaxDynamicSharedMemorySize, smem);
        int total = 2 * HWc;
        conv3_softmax_kernel<<<(total + 255) / 256, 256, smem>>>(
            x2, w_conv3, b_conv3, kern);
    }
    // spatially-variant 7x7 conv
    {
        dim3 grid(9, 9, 8);
        svconv_kernel<<<grid, 256>>>(key_high, kern, out);
    }
}